// round 1
// baseline (speedup 1.0000x reference)
#include <cuda_runtime.h>
#include <cuda_bf16.h>
#include <math.h>

// Problem constants
#define BATCH   8
#define SEQ     512
#define DMODEL  512
#define NHEAD   8
#define DHEAD   64
#define DFF     2048
#define NLAYER  6
#define DIN     64
#define MTOK    (BATCH * SEQ)          // 4096 token rows

// ---------------- scratch (static device globals; no allocation) ------------
__device__ float g_pe [SEQ * DMODEL];            // 1 MB
__device__ float g_x  [MTOK * DMODEL];           // 8 MB
__device__ float g_q  [MTOK * DMODEL];
__device__ float g_k  [MTOK * DMODEL];
__device__ float g_v  [MTOK * DMODEL];
__device__ float g_ctx[MTOK * DMODEL];
__device__ float g_tmp[MTOK * DMODEL];
__device__ float g_ffh[MTOK * DFF];              // 32 MB
__device__ float g_sc [BATCH * NHEAD * SEQ * SEQ]; // 64 MB

// ---------------- positional encoding table ---------------------------------
__global__ void pe_kernel(float* __restrict__ pe) {
    int s = blockIdx.x;          // 0..511
    int i = threadIdx.x;         // 0..255 (pairs)
    float div = expf(-(float)(2 * i) * (logf(10000.0f) / (float)DMODEL));
    float ang = (float)s * div;
    pe[s * DMODEL + 2 * i]     = sinf(ang);
    pe[s * DMODEL + 2 * i + 1] = cosf(ang);
}

// ---------------- generic GEMM: C[M,N] = A[M,K] @ B[K,N] + bias, epilogue ---
// Tile 128x64x16, 256 threads, 8x4 per thread. Requires M%128==0, N%64==0, K%16==0.
#define EPI_NONE 0
#define EPI_RELU 1
#define EPI_PE   2

__global__ __launch_bounds__(256)
void gemm_kernel(const float* __restrict__ A, const float* __restrict__ B,
                 const float* __restrict__ bias, float* __restrict__ C,
                 int M, int N, int K, int epi, float alpha,
                 const float* __restrict__ pe) {
    __shared__ float As[16][128];
    __shared__ float Bs[16][64];

    int tid = threadIdx.x;
    int tx = tid & 15, ty = tid >> 4;
    int row0 = blockIdx.y * 128;
    int col0 = blockIdx.x * 64;

    float acc[8][4];
#pragma unroll
    for (int i = 0; i < 8; i++)
#pragma unroll
        for (int j = 0; j < 4; j++) acc[i][j] = 0.0f;

    for (int k0 = 0; k0 < K; k0 += 16) {
        // A tile: 128x16 = 512 float4 loads, 2 per thread, store transposed
#pragma unroll
        for (int li = 0; li < 2; li++) {
            int idx = tid + li * 256;
            int r  = idx >> 2;
            int c4 = (idx & 3) * 4;
            float4 v = *(const float4*)&A[(size_t)(row0 + r) * K + k0 + c4];
            As[c4 + 0][r] = v.x; As[c4 + 1][r] = v.y;
            As[c4 + 2][r] = v.z; As[c4 + 3][r] = v.w;
        }
        // B tile: 16x64 = 256 float4 loads, 1 per thread
        {
            int r  = tid >> 4;
            int c4 = (tid & 15) * 4;
            *(float4*)&Bs[r][c4] = *(const float4*)&B[(size_t)(k0 + r) * N + col0 + c4];
        }
        __syncthreads();
#pragma unroll
        for (int k = 0; k < 16; k++) {
            float a[8], bb[4];
#pragma unroll
            for (int i = 0; i < 8; i++) a[i] = As[k][ty * 8 + i];
#pragma unroll
            for (int j = 0; j < 4; j++) bb[j] = Bs[k][tx * 4 + j];
#pragma unroll
            for (int i = 0; i < 8; i++)
#pragma unroll
                for (int j = 0; j < 4; j++) acc[i][j] += a[i] * bb[j];
        }
        __syncthreads();
    }

    int c = col0 + tx * 4;
    float4 bv = *(const float4*)&bias[c];
#pragma unroll
    for (int i = 0; i < 8; i++) {
        int r = row0 + ty * 8 + i;
        float4 o;
        o.x = acc[i][0] + bv.x; o.y = acc[i][1] + bv.y;
        o.z = acc[i][2] + bv.z; o.w = acc[i][3] + bv.w;
        if (epi == EPI_RELU) {
            o.x = fmaxf(o.x, 0.f); o.y = fmaxf(o.y, 0.f);
            o.z = fmaxf(o.z, 0.f); o.w = fmaxf(o.w, 0.f);
        } else if (epi == EPI_PE) {
            const float* per = pe + (size_t)(r & (SEQ - 1)) * DMODEL + c;
            float4 pv = *(const float4*)per;
            o.x = o.x * alpha + pv.x; o.y = o.y * alpha + pv.y;
            o.z = o.z * alpha + pv.z; o.w = o.w * alpha + pv.w;
        }
        *(float4*)&C[(size_t)r * N + c] = o;
    }
}

// ---------------- QK^T: E[bh,i,j] = scale * sum_d Q[b,i,h*64+d]*K[b,j,h*64+d]
// Tile 128x128, K=64, 256 threads, 8x8 per thread. grid (4,4,64)
__global__ __launch_bounds__(256)
void qk_kernel(const float* __restrict__ Q, const float* __restrict__ Km,
               float* __restrict__ E, float scale) {
    __shared__ float As[16][128];
    __shared__ float Bs[16][128];

    int tid = threadIdx.x;
    int tx = tid & 15, ty = tid >> 4;
    int z = blockIdx.z;
    int b = z >> 3, h = z & 7;
    const float* qb = Q  + (size_t)b * SEQ * DMODEL + h * DHEAD;
    const float* kb = Km + (size_t)b * SEQ * DMODEL + h * DHEAD;
    float* eb = E + (size_t)z * SEQ * SEQ;
    int row0 = blockIdx.y * 128;
    int col0 = blockIdx.x * 128;

    float acc[8][8];
#pragma unroll
    for (int i = 0; i < 8; i++)
#pragma unroll
        for (int j = 0; j < 8; j++) acc[i][j] = 0.0f;

    for (int k0 = 0; k0 < DHEAD; k0 += 16) {
#pragma unroll
        for (int li = 0; li < 2; li++) {
            int idx = tid + li * 256;
            int r  = idx >> 2;
            int c4 = (idx & 3) * 4;
            float4 va = *(const float4*)&qb[(size_t)(row0 + r) * DMODEL + k0 + c4];
            As[c4 + 0][r] = va.x; As[c4 + 1][r] = va.y;
            As[c4 + 2][r] = va.z; As[c4 + 3][r] = va.w;
            float4 vb = *(const float4*)&kb[(size_t)(col0 + r) * DMODEL + k0 + c4];
            Bs[c4 + 0][r] = vb.x; Bs[c4 + 1][r] = vb.y;
            Bs[c4 + 2][r] = vb.z; Bs[c4 + 3][r] = vb.w;
        }
        __syncthreads();
#pragma unroll
        for (int k = 0; k < 16; k++) {
            float a[8], bb[8];
#pragma unroll
            for (int i = 0; i < 8; i++) a[i]  = As[k][ty * 8 + i];
#pragma unroll
            for (int j = 0; j < 8; j++) bb[j] = Bs[k][tx * 8 + j];
#pragma unroll
            for (int i = 0; i < 8; i++)
#pragma unroll
                for (int j = 0; j < 8; j++) acc[i][j] += a[i] * bb[j];
        }
        __syncthreads();
    }

#pragma unroll
    for (int i = 0; i < 8; i++) {
        int r = row0 + ty * 8 + i;
#pragma unroll
        for (int j4 = 0; j4 < 2; j4++) {
            float4 o;
            o.x = acc[i][j4 * 4 + 0] * scale;
            o.y = acc[i][j4 * 4 + 1] * scale;
            o.z = acc[i][j4 * 4 + 2] * scale;
            o.w = acc[i][j4 * 4 + 3] * scale;
            *(float4*)&eb[(size_t)r * SEQ + col0 + tx * 8 + j4 * 4] = o;
        }
    }
}

// ---------------- softmax over last dim (512), one block per row ------------
__global__ __launch_bounds__(128)
void softmax_kernel(float* __restrict__ sc) {
    __shared__ float red[128];
    int row = blockIdx.x;
    float4* p = (float4*)(sc + (size_t)row * SEQ);
    float4 v = p[threadIdx.x];
    float m = fmaxf(fmaxf(v.x, v.y), fmaxf(v.z, v.w));
    red[threadIdx.x] = m;
    __syncthreads();
    for (int s = 64; s > 0; s >>= 1) {
        if (threadIdx.x < s) red[threadIdx.x] = fmaxf(red[threadIdx.x], red[threadIdx.x + s]);
        __syncthreads();
    }
    m = red[0];
    __syncthreads();
    v.x = __expf(v.x - m); v.y = __expf(v.y - m);
    v.z = __expf(v.z - m); v.w = __expf(v.w - m);
    red[threadIdx.x] = v.x + v.y + v.z + v.w;
    __syncthreads();
    for (int s = 64; s > 0; s >>= 1) {
        if (threadIdx.x < s) red[threadIdx.x] += red[threadIdx.x + s];
        __syncthreads();
    }
    float inv = 1.0f / red[0];
    v.x *= inv; v.y *= inv; v.z *= inv; v.w *= inv;
    p[threadIdx.x] = v;
}

// ---------------- attn @ V: C[b,i,h*64+d] = sum_j P[bh,i,j] * V[b,j,h*64+d] -
// Tile 128x64x16, 256 threads, 8x4. grid (4,1,64)
__global__ __launch_bounds__(256)
void av_kernel(const float* __restrict__ P, const float* __restrict__ V,
               float* __restrict__ C) {
    __shared__ float As[16][128];
    __shared__ float Bs[16][64];

    int tid = threadIdx.x;
    int tx = tid & 15, ty = tid >> 4;
    int z = blockIdx.z;
    int b = z >> 3, h = z & 7;
    const float* pb = P + (size_t)z * SEQ * SEQ;
    const float* vb = V + (size_t)b * SEQ * DMODEL + h * DHEAD;
    float* cb = C + (size_t)b * SEQ * DMODEL + h * DHEAD;
    int row0 = blockIdx.x * 128;

    float acc[8][4];
#pragma unroll
    for (int i = 0; i < 8; i++)
#pragma unroll
        for (int j = 0; j < 4; j++) acc[i][j] = 0.0f;

    for (int k0 = 0; k0 < SEQ; k0 += 16) {
#pragma unroll
        for (int li = 0; li < 2; li++) {
            int idx = tid + li * 256;
            int r  = idx >> 2;
            int c4 = (idx & 3) * 4;
            float4 v = *(const float4*)&pb[(size_t)(row0 + r) * SEQ + k0 + c4];
            As[c4 + 0][r] = v.x; As[c4 + 1][r] = v.y;
            As[c4 + 2][r] = v.z; As[c4 + 3][r] = v.w;
        }
        {
            int r  = tid >> 4;
            int c4 = (tid & 15) * 4;
            *(float4*)&Bs[r][c4] = *(const float4*)&vb[(size_t)(k0 + r) * DMODEL + c4];
        }
        __syncthreads();
#pragma unroll
        for (int k = 0; k < 16; k++) {
            float a[8], bb[4];
#pragma unroll
            for (int i = 0; i < 8; i++) a[i]  = As[k][ty * 8 + i];
#pragma unroll
            for (int j = 0; j < 4; j++) bb[j] = Bs[k][tx * 4 + j];
#pragma unroll
            for (int i = 0; i < 8; i++)
#pragma unroll
                for (int j = 0; j < 4; j++) acc[i][j] += a[i] * bb[j];
        }
        __syncthreads();
    }

#pragma unroll
    for (int i = 0; i < 8; i++) {
        float4 o;
        o.x = acc[i][0]; o.y = acc[i][1]; o.z = acc[i][2]; o.w = acc[i][3];
        *(float4*)&cb[(size_t)(row0 + ty * 8 + i) * DMODEL + tx * 4] = o;
    }
}

// ---------------- residual + layernorm, one block per token row -------------
__global__ __launch_bounds__(128)
void ln_kernel(const float* __restrict__ x, const float* __restrict__ res,
               const float* __restrict__ gs, const float* __restrict__ gb,
               float* __restrict__ out) {
    __shared__ float red[128];
    int row = blockIdx.x;
    int t = threadIdx.x;
    float4 a = *(const float4*)&x  [(size_t)row * DMODEL + t * 4];
    float4 r = *(const float4*)&res[(size_t)row * DMODEL + t * 4];
    float y0 = a.x + r.x, y1 = a.y + r.y, y2 = a.z + r.z, y3 = a.w + r.w;

    red[t] = y0 + y1 + y2 + y3;
    __syncthreads();
    for (int s = 64; s > 0; s >>= 1) {
        if (t < s) red[t] += red[t + s];
        __syncthreads();
    }
    float mu = red[0] * (1.0f / DMODEL);
    __syncthreads();

    float d0 = y0 - mu, d1 = y1 - mu, d2 = y2 - mu, d3 = y3 - mu;
    red[t] = d0 * d0 + d1 * d1 + d2 * d2 + d3 * d3;
    __syncthreads();
    for (int s = 64; s > 0; s >>= 1) {
        if (t < s) red[t] += red[t + s];
        __syncthreads();
    }
    float k = rsqrtf(red[0] * (1.0f / DMODEL) + 1e-5f);

    float4 sv = *(const float4*)&gs[t * 4];
    float4 bv = *(const float4*)&gb[t * 4];
    float4 o;
    o.x = d0 * k * sv.x + bv.x;
    o.y = d1 * k * sv.y + bv.y;
    o.z = d2 * k * sv.z + bv.z;
    o.w = d3 * k * sv.w + bv.w;
    *(float4*)&out[(size_t)row * DMODEL + t * 4] = o;
}

// ---------------- host orchestration ----------------------------------------
static inline void launch_gemm(const float* A, const float* B, const float* bias,
                               float* C, int M, int N, int K, int epi,
                               float alpha, const float* pe) {
    dim3 grid(N / 64, M / 128);
    gemm_kernel<<<grid, 256>>>(A, B, bias, C, M, N, K, epi, alpha, pe);
}

extern "C" void kernel_launch(void* const* d_in, const int* in_sizes, int n_in,
                              void* d_out, int out_size) {
    const float* source = (const float*)d_in[0];
    // d_in[1] = mask (unused by reference)
    const float* fin_w1 = (const float*)d_in[2];
    const float* fin_b1 = (const float*)d_in[3];
    const float* fin_w2 = (const float*)d_in[4];
    const float* fin_b2 = (const float*)d_in[5];
    const float* wq = (const float*)d_in[6];
    const float* bq = (const float*)d_in[7];
    const float* wk = (const float*)d_in[8];
    const float* bk = (const float*)d_in[9];
    const float* wv = (const float*)d_in[10];
    const float* bv = (const float*)d_in[11];
    const float* wo = (const float*)d_in[12];
    const float* bo = (const float*)d_in[13];
    const float* n1s = (const float*)d_in[14];
    const float* n1b = (const float*)d_in[15];
    const float* ffw1 = (const float*)d_in[16];
    const float* ffb1 = (const float*)d_in[17];
    const float* ffw2 = (const float*)d_in[18];
    const float* ffb2 = (const float*)d_in[19];
    const float* n2s = (const float*)d_in[20];
    const float* n2b = (const float*)d_in[21];
    float* out = (float*)d_out;

    float *px, *pq, *pk, *pv, *pctx, *ptmp, *pffh, *psc, *ppe;
    cudaGetSymbolAddress((void**)&px,   g_x);
    cudaGetSymbolAddress((void**)&pq,   g_q);
    cudaGetSymbolAddress((void**)&pk,   g_k);
    cudaGetSymbolAddress((void**)&pv,   g_v);
    cudaGetSymbolAddress((void**)&pctx, g_ctx);
    cudaGetSymbolAddress((void**)&ptmp, g_tmp);
    cudaGetSymbolAddress((void**)&pffh, g_ffh);
    cudaGetSymbolAddress((void**)&psc,  g_sc);
    cudaGetSymbolAddress((void**)&ppe,  g_pe);

    const float sqrtd = 22.627416998f;        // sqrt(512)
    const float scale = 0.044194173824f;      // 1/sqrt(512)

    // positional encoding table
    pe_kernel<<<SEQ, 256>>>(ppe);

    // input FFN: relu(source @ fin_w1 + b1) @ fin_w2 + b2, * sqrt(d) + pe
    launch_gemm(source, fin_w1, fin_b1, pffh, MTOK, DFF, DIN, EPI_RELU, 0.f, nullptr);
    launch_gemm(pffh, fin_w2, fin_b2, px, MTOK, DMODEL, DFF, EPI_PE, sqrtd, ppe);

    for (int l = 0; l < NLAYER; l++) {
        const float* wql = wq + (size_t)l * DMODEL * DMODEL;
        const float* wkl = wk + (size_t)l * DMODEL * DMODEL;
        const float* wvl = wv + (size_t)l * DMODEL * DMODEL;
        const float* wol = wo + (size_t)l * DMODEL * DMODEL;
        const float* f1l = ffw1 + (size_t)l * DMODEL * DFF;
        const float* f2l = ffw2 + (size_t)l * DFF * DMODEL;

        launch_gemm(px, wql, bq + l * DMODEL, pq, MTOK, DMODEL, DMODEL, EPI_NONE, 0.f, nullptr);
        launch_gemm(px, wkl, bk + l * DMODEL, pk, MTOK, DMODEL, DMODEL, EPI_NONE, 0.f, nullptr);
        launch_gemm(px, wvl, bv + l * DMODEL, pv, MTOK, DMODEL, DMODEL, EPI_NONE, 0.f, nullptr);

        {
            dim3 grid(SEQ / 128, SEQ / 128, BATCH * NHEAD);
            qk_kernel<<<grid, 256>>>(pq, pk, psc, scale);
        }
        softmax_kernel<<<BATCH * NHEAD * SEQ, 128>>>(psc);
        {
            dim3 grid(SEQ / 128, 1, BATCH * NHEAD);
            av_kernel<<<grid, 256>>>(psc, pv, pctx);
        }

        launch_gemm(pctx, wol, bo + l * DMODEL, ptmp, MTOK, DMODEL, DMODEL, EPI_NONE, 0.f, nullptr);
        ln_kernel<<<MTOK, 128>>>(px, ptmp, n1s + l * DMODEL, n1b + l * DMODEL, px);

        launch_gemm(px, f1l, ffb1 + l * DFF, pffh, MTOK, DFF, DMODEL, EPI_RELU, 0.f, nullptr);
        launch_gemm(pffh, f2l, ffb2 + l * DMODEL, ptmp, MTOK, DMODEL, DFF, EPI_NONE, 0.f, nullptr);

        float* lnout = (l == NLAYER - 1) ? out : px;
        ln_kernel<<<MTOK, 128>>>(px, ptmp, n2s + l * DMODEL, n2b + l * DMODEL, lnout);
    }
}